// round 10
// baseline (speedup 1.0000x reference)
#include <cuda_runtime.h>
#include <cstdint>
#include <math.h>

#define T_FRAMES 1001
#define BATCH    16
#define LSIG     240000
#define HOP      240
#define DIN      301
#define HID      128
#define DOUTN    64
#define NROWS    (T_FRAMES*BATCH)   // 16016

typedef unsigned long long ull;
typedef unsigned int u32;

// ------------------------- static device scratch -------------------------
__device__ float2 g_tw[1024];                  // twiddles e^{-2pi i k/2048}
__device__ float  g_win[2048];                 // padded Hann window
__device__ float  g_feat[NROWS * DIN];         // features [row=t*16+b][301]
__device__ float  g_wihT[DIN * 1024];          // transposed input weights [k][g]
__device__ float  g_bias[1024];
__device__ float  g_pre[NROWS * 1024];         // pre-activations [row][1024]
__device__ float2 g_whhP[2 * 64 * 512];        // [d][k2][g] = (W[g][2k2], W[g][2k2+1])
__device__ float  g_hcat[NROWS * 256];         // [row][fwd 0..127 | bwd 128..255]
__device__ float  g_owT[256 * 64];             // out_w transposed [k][o]

// ------------------------------ prep kernel ------------------------------
__global__ void prep_kernel(const float* __restrict__ wihf, const float* __restrict__ whhf,
                            const float* __restrict__ bf,   const float* __restrict__ wihb,
                            const float* __restrict__ whhb, const float* __restrict__ bb,
                            const float* __restrict__ outw)
{
    int tid = blockIdx.x * blockDim.x + threadIdx.x;
    int nth = gridDim.x * blockDim.x;

    for (int k = tid; k < 1024; k += nth) {
        float s, c;
        sincospif((float)k * (1.0f/1024.0f), &s, &c);
        g_tw[k] = make_float2(c, -s);
    }
    for (int j = tid; j < 2048; j += nth) {
        int jw = j - 544;
        g_win[j] = (jw >= 0 && jw < 960) ? (0.5f - 0.5f*cospif((float)jw * (1.0f/480.0f))) : 0.0f;
    }
    for (int i = tid; i < DIN*1024; i += nth) {
        int g = i & 1023, k = i >> 10;
        g_wihT[i] = (g < 512) ? wihf[g*DIN + k] : wihb[(g-512)*DIN + k];
    }
    for (int g = tid; g < 1024; g += nth)
        g_bias[g] = (g < 512) ? bf[g] : bb[g-512];
    for (int i = tid; i < 2*64*512; i += nth) {
        int d = i >> 15;
        int k2 = (i >> 9) & 63;
        int g = i & 511;
        const float* W = d ? whhb : whhf;
        g_whhP[i] = make_float2(W[g*HID + 2*k2], W[g*HID + 2*k2 + 1]);
    }
    for (int i = tid; i < 256*64; i += nth) {
        int o = i & 63, k = i >> 6;
        g_owT[i] = outw[o*256 + k];
    }
}

// ---------------------- STFT (real-packed) + features ---------------------
__device__ __forceinline__ float wsamp(const float* __restrict__ xb, int t, int j)
{
    int q = t*HOP + j - 1024;
    if (q < 0) q = -q;
    else if (q >= LSIG) q = 2*LSIG - 2 - q;
    return xb[q] * g_win[j];
}

__global__ __launch_bounds__(256) void stft_kernel(const float* __restrict__ x,
                                                   const float* __restrict__ f0)
{
    __shared__ float2 S[1024];
    int t = blockIdx.x, b = blockIdx.y, tid = threadIdx.x;
    const float* xb = x + b * LSIG;

    // pack even/odd windowed samples into 1024 complex, bit-reversed (10 bit)
    for (int n = tid; n < 1024; n += 256) {
        float v0 = wsamp(xb, t, 2*n);
        float v1 = wsamp(xb, t, 2*n + 1);
        int rev = __brev((unsigned)n) >> 22;
        S[rev] = make_float2(v0, v1);
    }
    __syncthreads();

    // 10-stage radix-2 DIT on 1024 complex
    #pragma unroll
    for (int s = 1; s <= 10; s++) {
        int half = 1 << (s-1);
        for (int idx = tid; idx < 512; idx += 256) {
            int pos = idx & (half - 1);
            int grp = idx >> (s-1);
            int i0 = (grp << s) + pos;
            int i1 = i0 + half;
            float2 tw = g_tw[pos << (11 - s)];
            float2 u = S[i0], v = S[i1];
            float tr = tw.x*v.x - tw.y*v.y;
            float ti = tw.x*v.y + tw.y*v.x;
            S[i0] = make_float2(u.x + tr, u.y + ti);
            S[i1] = make_float2(u.x - tr, u.y - ti);
        }
        __syncthreads();
    }

    // harmonic gather with real-FFT unpack: X[k] = Xe[k] + e^{-i pi k/1024} Xo[k]
    // unpack twiddle e^{-i pi k/1024} == g_tw[k]
    float f0v = f0[b*T_FRAMES + t];
    float f0nz = (f0v > 0.0f) ? f0v : 80.0f;
    int rowbase = (t*BATCH + b) * DIN;
    for (int j = tid; j < 300; j += 256) {
        float m = 0.5f * (float)(j + 1);
        float harm = f0nz * m;
        float r = harm / 11.71875f;
        int k = (int)rintf(r);
        k = min(max(k, 0), 1024);
        float p = 0.0f;
        if (k < 1024) {
            int kr = (1024 - k) & 1023;
            float2 a = S[k];
            float2 zr = S[kr];
            float br = zr.x, bi = -zr.y;                 // conj(Z[N-k])
            float xer = 0.5f*(a.x + br), xei = 0.5f*(a.y + bi);
            float dr = a.x - br, di = a.y - bi;
            float xo_r = 0.5f*di, xo_i = -0.5f*dr;       // -i*(a-b)/2
            float2 tww = g_tw[k];
            float wr = tww.x, wi = tww.y;
            float Xr = xer + wr*xo_r - wi*xo_i;
            float Xi = xei + wr*xo_i + wi*xo_r;
            p = Xr*Xr + Xi*Xi;
        }
        g_feat[rowbase + j] = (logf(p + 1e-8f) + 18.0f) / 23.0f;
    }
    if (tid == 0) g_feat[rowbase + 300] = logf(f0nz);
}

// ---------------------------- input pre-GEMM (f32x2) ----------------------
__device__ __forceinline__ ull ffma2(ull a, ull b, ull c) {
    ull d;
    asm("fma.rn.f32x2 %0, %1, %2, %3;" : "=l"(d) : "l"(a), "l"(b), "l"(c));
    return d;
}
__device__ __forceinline__ ull packff(float f) {
    ull d;
    asm("mov.b64 %0, {%1, %1};" : "=l"(d) : "f"(f));
    return d;
}

__global__ __launch_bounds__(256) void pre_gemm_kernel()
{
    __shared__ float s_feat[16 * DIN];
    int t = blockIdx.x;
    int cb = blockIdx.y * 512;
    int tid = threadIdx.x;

    int base = t * 16 * DIN;
    for (int i = tid; i < 16*DIN; i += 256) s_feat[i] = g_feat[base + i];
    __syncthreads();

    int cl = (tid & 63) * 8 + cb;    // 8 consecutive cols
    int rh = tid >> 6;               // rows rh*4 .. rh*4+3
    ull acc[4][4];
    {
        const ull* bp = (const ull*)&g_bias[cl];
        ull b0 = bp[0], b1 = bp[1], b2 = bp[2], b3 = bp[3];
        #pragma unroll
        for (int r = 0; r < 4; r++) { acc[r][0]=b0; acc[r][1]=b1; acc[r][2]=b2; acc[r][3]=b3; }
    }

    const float* fb = s_feat + rh*4*DIN;
    for (int k = 0; k < DIN; k++) {
        const ull* wp = (const ull*)&g_wihT[k*1024 + cl];
        ull w0 = wp[0], w1 = wp[1], w2 = wp[2], w3 = wp[3];
        #pragma unroll
        for (int r = 0; r < 4; r++) {
            ull ff = packff(fb[r*DIN + k]);
            acc[r][0] = ffma2(w0, ff, acc[r][0]);
            acc[r][1] = ffma2(w1, ff, acc[r][1]);
            acc[r][2] = ffma2(w2, ff, acc[r][2]);
            acc[r][3] = ffma2(w3, ff, acc[r][3]);
        }
    }
    #pragma unroll
    for (int r = 0; r < 4; r++) {
        int row = t*16 + rh*4 + r;
        ull* op = (ull*)&g_pre[row*1024 + cl];
        op[0]=acc[r][0]; op[1]=acc[r][1]; op[2]=acc[r][2]; op[3]=acc[r][3];
    }
}

// ------------------------------ bi-LSTM ----------------------------------
// fast, overflow-safe sigmoid/tanh via MUFU (EX2 + RCP), rel err ~1e-6
__device__ __forceinline__ float fsigm(float x) {
    float e = __expf(-fabsf(x));
    float inv = __fdividef(1.0f, 1.0f + e);
    return (x >= 0.0f) ? inv : e * inv;
}
__device__ __forceinline__ float ftanh(float x) {
    float e = __expf(-2.0f * fabsf(x));
    float r = __fdividef(1.0f - e, 1.0f + e);
    return copysignf(r, x);
}
__device__ __forceinline__ float2 u2f2(ull a) {
    float2 f;
    asm("mov.b64 {%0, %1}, %2;" : "=f"(f.x), "=f"(f.y) : "l"(a));
    return f;
}
#define CLUSTER_SYNC() do { \
    asm volatile("barrier.cluster.arrive.aligned;" ::: "memory"); \
    asm volatile("barrier.cluster.wait.aligned;"   ::: "memory"); \
} while (0)

// cluster of 2 CTAs per (b, d): k-split, register-resident weights.
// Per-step exchange: 16 eager per-warp 128B cp.async.bulk copies (issued as
// each warp's partials are ready) completing on the peer's parity mbarrier;
// the block-wide __syncthreads (needed for LOCAL partial visibility) overlaps
// the DSMEM flight. Expects armed 2 steps ahead.
__global__ __launch_bounds__(512, 1) __cluster_dims__(2, 1, 1)
void lstm_kernel()
{
    int cid  = blockIdx.x >> 1;      // 0..31
    int rank = blockIdx.x & 1;       // k-half
    int d = cid >> 4, b = cid & 15;
    int g = threadIdx.x;             // gate row 0..511

    // 64 weights (this rank's k-half of row g) as 32 packed f32x2 registers
    ull w2[32];
    {
        const ull* WP = (const ull*)g_whhP + (size_t)(d*64 + rank*32)*512 + g;
        #pragma unroll
        for (int j = 0; j < 32; j++) w2[j] = WP[j*512];
    }

    __shared__ __align__(16) ull   h2_sh[64];          // current h (128 floats)
    __shared__ __align__(16) float partbuf[2][2][512]; // [parity][src-rank][g]
    __shared__ __align__(8)  ull   s_bar[2];           // parity-indexed mbarriers

    if (g < 64) h2_sh[g] = 0ULL;
    u32 bar_local  = (u32)__cvta_generic_to_shared(s_bar);
    u32 part_local = (u32)__cvta_generic_to_shared(partbuf);
    if (g == 0) {
        asm volatile("mbarrier.init.shared.b64 [%0], 1;" :: "r"(bar_local)     : "memory");
        asm volatile("mbarrier.init.shared.b64 [%0], 1;" :: "r"(bar_local + 8) : "memory");
        // arm steps 0 and 1 (2048B peer bytes each) before any peer traffic
        asm volatile("mbarrier.arrive.expect_tx.shared.b64 _, [%0], %1;"
                     :: "r"(bar_local),     "r"(2048u) : "memory");
        asm volatile("mbarrier.arrive.expect_tx.shared.b64 _, [%0], %1;"
                     :: "r"(bar_local + 8), "r"(2048u) : "memory");
    }
    float c_state = 0.0f;
    __syncthreads();
    CLUSTER_SYNC();   // peer barriers armed before any bulk copy

    // cluster-mapped peer addresses (hoisted)
    u32 part_peer_c, bar_peer_c;
    asm("mapa.shared::cluster.u32 %0, %1, %2;" : "=r"(part_peer_c) : "r"(part_local), "r"((u32)(rank^1)));
    asm("mapa.shared::cluster.u32 %0, %1, %2;" : "=r"(bar_peer_c)  : "r"(bar_local),  "r"((u32)(rank^1)));
    // this thread's warp chunk offset within a parity buffer
    u32 wchunk = (u32)rank*2048u + ((u32)g >> 5)*128u;

    const float* preB = g_pre + d*512;
    float* hcatB = g_hcat + d*HID;

    // prefetch pre-activations for step 0
    float pn0 = 0.f, pn1 = 0.f, pn2 = 0.f, pn3 = 0.f;
    if (g < HID) {
        int t0 = d ? (T_FRAMES - 1) : 0;
        const float* pr = preB + (size_t)(t0*BATCH + b)*1024 + g;
        pn0 = pr[0]; pn1 = pr[128]; pn2 = pr[256]; pn3 = pr[384];
    }

    for (int s = 0; s < T_FRAMES; s++) {
        int t = d ? (T_FRAMES - 1 - s) : s;
        int row = t*BATCH + b;
        u32 par = (u32)(s & 1);
        u32 ph  = (u32)((s >> 1) & 1);

        float p0 = pn0, p1 = pn1, p2 = pn2, p3 = pn3;
        // prefetch NEXT step's pre-activations — a full step of latency overlap
        if (g < HID && s + 1 < T_FRAMES) {
            int tn = d ? (T_FRAMES - 2 - s) : (s + 1);
            const float* pr = preB + (size_t)(tn*BATCH + b)*1024 + g;
            pn0 = pr[0]; pn1 = pr[128]; pn2 = pr[256]; pn3 = pr[384];
        }

        // partial dot over this rank's k-half: 32 packed FFMA2
        ull a0 = 0ULL, a1 = 0ULL, a2 = 0ULL, a3 = 0ULL;
        const ulonglong2* hh = (const ulonglong2*)(h2_sh + rank*32);
        #pragma unroll
        for (int j = 0; j < 8; j++) {
            ulonglong2 hA = hh[2*j], hB = hh[2*j+1];
            a0 = ffma2(w2[4*j+0], hA.x, a0);
            a1 = ffma2(w2[4*j+1], hA.y, a1);
            a2 = ffma2(w2[4*j+2], hB.x, a2);
            a3 = ffma2(w2[4*j+3], hB.y, a3);
        }
        float2 f0v = u2f2(a0), f1v = u2f2(a1), f2v = u2f2(a2), f3v = u2f2(a3);
        float partial = ((f0v.x + f0v.y) + (f1v.x + f1v.y))
                      + ((f2v.x + f2v.y) + (f3v.x + f3v.y));

        partbuf[par][rank][g] = partial;      // local STS
        __syncwarp();                         // warp's 32 partials complete

        if ((g & 31) == 0) {                  // eager per-warp 128B publish
            asm volatile("fence.proxy.async.shared::cta;" ::: "memory");
            u32 off = par*4096u + wchunk;
            asm volatile("cp.async.bulk.shared::cluster.shared::cta.mbarrier::complete_tx::bytes "
                         "[%0], [%1], %2, [%3];"
                         :: "r"(part_peer_c + off), "r"(part_local + off),
                            "r"(128u), "r"(bar_peer_c + 8u*par) : "memory");
        }

        __syncthreads();   // local partials visible to gate threads (overlaps DSMEM)

        // wait for the peer's 2048B of this step
        asm volatile("{\n\t"
                     ".reg .pred P;\n"
                     "LW%=:\n\t"
                     "mbarrier.try_wait.parity.acquire.cta.shared::cta.b64 P, [%0], %1, 0x989680;\n\t"
                     "@!P bra LW%=;\n\t"
                     "}" :: "r"(bar_local + 8u*par), "r"(ph) : "memory");

        // re-arm this parity barrier for step s+2 (provably before peer can send it)
        if (g == 0 && s + 2 < T_FRAMES) {
            asm volatile("mbarrier.arrive.expect_tx.shared.b64 _, [%0], %1;"
                         :: "r"(bar_local + 8u*par), "r"(2048u) : "memory");
        }

        if (g < HID) {
            const float* lo = partbuf[par][0];   // k-low half (rank 0)
            const float* hi = partbuf[par][1];   // k-high half (rank 1)
            float zi = (lo[g]     + hi[g])     + p0;
            float zf = (lo[g+128] + hi[g+128]) + p1;
            float zg = (lo[g+256] + hi[g+256]) + p2;
            float zo = (lo[g+384] + hi[g+384]) + p3;
            c_state = fsigm(zf)*c_state + fsigm(zi)*ftanh(zg);
            float h = fsigm(zo)*ftanh(c_state);
            ((float*)h2_sh)[g] = h;
            if (rank == 0) hcatB[(size_t)row*256 + g] = h;
        }
        __syncthreads();   // h2_sh ready for next step's dot
    }
    CLUSTER_SYNC();        // no CTA exits with peer traffic in flight
}

// ----------------------- LayerNorm + output GEMM --------------------------
__global__ __launch_bounds__(256) void final_kernel(const float* __restrict__ ln_g,
                                                    const float* __restrict__ ln_b,
                                                    const float* __restrict__ out_b,
                                                    float* __restrict__ out)
{
    __shared__ float sh[16*256];
    __shared__ float s_sum[256], s_sq[256];
    __shared__ float s_mu[16], s_rstd[16];

    int t = blockIdx.x, tid = threadIdx.x;
    for (int i = tid; i < 4096; i += 256) sh[i] = g_hcat[t*4096 + i];
    __syncthreads();

    {
        int row = tid >> 4, seg = tid & 15;
        float sm = 0.f, sq = 0.f;
        const float* p = sh + row*256 + seg*16;
        #pragma unroll
        for (int u = 0; u < 16; u++) { float v = p[u]; sm += v; sq += v*v; }
        s_sum[tid] = sm; s_sq[tid] = sq;
    }
    __syncthreads();
    if (tid < 16) {
        float sm = 0.f, sq = 0.f;
        #pragma unroll
        for (int u = 0; u < 16; u++) { sm += s_sum[tid*16 + u]; sq += s_sq[tid*16 + u]; }
        float mu = sm * (1.0f/256.0f);
        float var = sq * (1.0f/256.0f) - mu*mu;
        s_mu[tid] = mu;
        s_rstd[tid] = rsqrtf(var + 1e-5f);
    }
    __syncthreads();
    for (int i = tid; i < 4096; i += 256) {
        int r = i >> 8, k = i & 255;
        sh[i] = (sh[i] - s_mu[r]) * s_rstd[r] * ln_g[k] + ln_b[k];
    }
    __syncthreads();

    int col = tid & 63, rg = tid >> 6;
    float acc[4];
    float bb = out_b[col];
    #pragma unroll
    for (int r = 0; r < 4; r++) acc[r] = bb;
    for (int k = 0; k < 256; k++) {
        float w = g_owT[k*64 + col];
        #pragma unroll
        for (int r = 0; r < 4; r++) acc[r] += sh[(rg*4 + r)*256 + k] * w;
    }
    #pragma unroll
    for (int r = 0; r < 4; r++) {
        int b = rg*4 + r;
        out[(b*T_FRAMES + t)*DOUTN + col] = acc[r];
    }
}

// ------------------------------ launcher ----------------------------------
extern "C" void kernel_launch(void* const* d_in, const int* in_sizes, int n_in,
                              void* d_out, int out_size)
{
    const float* x     = (const float*)d_in[0];
    const float* f0    = (const float*)d_in[1];
    const float* wihf  = (const float*)d_in[2];
    const float* whhf  = (const float*)d_in[3];
    const float* bf    = (const float*)d_in[4];
    const float* wihb  = (const float*)d_in[5];
    const float* whhb  = (const float*)d_in[6];
    const float* bb    = (const float*)d_in[7];
    const float* lng   = (const float*)d_in[8];
    const float* lnb   = (const float*)d_in[9];
    const float* outw  = (const float*)d_in[10];
    const float* outb  = (const float*)d_in[11];
    float* out = (float*)d_out;

    prep_kernel<<<256, 256>>>(wihf, whhf, bf, wihb, whhb, bb, outw);
    stft_kernel<<<dim3(T_FRAMES, BATCH), 256>>>(x, f0);
    pre_gemm_kernel<<<dim3(T_FRAMES, 2), 256>>>();
    lstm_kernel<<<64, 512>>>();
    final_kernel<<<T_FRAMES, 256>>>(lng, lnb, outb, out);
}

// round 11
// speedup vs baseline: 1.2396x; 1.2396x over previous
#include <cuda_runtime.h>
#include <cstdint>
#include <math.h>

#define T_FRAMES 1001
#define BATCH    16
#define LSIG     240000
#define HOP      240
#define DIN      301
#define HID      128
#define DOUTN    64
#define NROWS    (T_FRAMES*BATCH)   // 16016

typedef unsigned long long ull;
typedef unsigned int u32;

// ------------------------- static device scratch -------------------------
__device__ float2 g_tw[1024];                  // twiddles e^{-2pi i k/2048}
__device__ float  g_feat[NROWS * DIN];         // features [row=t*16+b][301]
__device__ float  g_wihT[DIN * 1024];          // transposed input weights [k][g]
__device__ float  g_bias[1024];
__device__ float  g_pre[NROWS * 1024];         // pre-activations [row][1024]
__device__ float2 g_whhP[2 * 64 * 512];        // [d][k2][g] = (W[g][2k2], W[g][2k2+1])
__device__ float  g_hcat[NROWS * 256];         // [row][fwd 0..127 | bwd 128..255]
__device__ float  g_owT[256 * 64];             // out_w transposed [k][o]

// ------------------------------ prep kernel ------------------------------
__global__ void prep_kernel(const float* __restrict__ wihf, const float* __restrict__ whhf,
                            const float* __restrict__ bf,   const float* __restrict__ wihb,
                            const float* __restrict__ whhb, const float* __restrict__ bb,
                            const float* __restrict__ outw)
{
    int tid = blockIdx.x * blockDim.x + threadIdx.x;
    int nth = gridDim.x * blockDim.x;

    for (int k = tid; k < 1024; k += nth) {
        float s, c;
        sincospif((float)k * (1.0f/1024.0f), &s, &c);
        g_tw[k] = make_float2(c, -s);
    }
    for (int i = tid; i < DIN*1024; i += nth) {
        int g = i & 1023, k = i >> 10;
        g_wihT[i] = (g < 512) ? wihf[g*DIN + k] : wihb[(g-512)*DIN + k];
    }
    for (int g = tid; g < 1024; g += nth)
        g_bias[g] = (g < 512) ? bf[g] : bb[g-512];
    for (int i = tid; i < 2*64*512; i += nth) {
        int d = i >> 15;
        int k2 = (i >> 9) & 63;
        int g = i & 511;
        const float* W = d ? whhb : whhf;
        g_whhP[i] = make_float2(W[g*HID + 2*k2], W[g*HID + 2*k2 + 1]);
    }
    for (int i = tid; i < 256*64; i += nth) {
        int o = i & 63, k = i >> 6;
        g_owT[i] = outw[o*256 + k];
    }
}

// ---------------------- STFT (real-packed) + features ---------------------
__device__ __forceinline__ float wsamp(const float* __restrict__ xb, int t, int j)
{
    int q = t*HOP + j - 1024;
    if (q < 0) q = -q;
    else if (q >= LSIG) q = 2*LSIG - 2 - q;
    int jw = j - 544;
    float wv = (jw >= 0 && jw < 960) ? (0.5f - 0.5f*cospif((float)jw * (1.0f/480.0f))) : 0.0f;
    return xb[q] * wv;
}

__global__ __launch_bounds__(256) void stft_kernel(const float* __restrict__ x,
                                                   const float* __restrict__ f0)
{
    __shared__ float2 S[1024];
    int t = blockIdx.x, b = blockIdx.y, tid = threadIdx.x;
    const float* xb = x + b * LSIG;

    // pack even/odd windowed samples into 1024 complex, bit-reversed (10 bit)
    for (int n = tid; n < 1024; n += 256) {
        float v0 = wsamp(xb, t, 2*n);
        float v1 = wsamp(xb, t, 2*n + 1);
        int rev = __brev((unsigned)n) >> 22;
        S[rev] = make_float2(v0, v1);
    }
    __syncthreads();

    // 10-stage radix-2 DIT on 1024 complex
    #pragma unroll
    for (int s = 1; s <= 10; s++) {
        int half = 1 << (s-1);
        for (int idx = tid; idx < 512; idx += 256) {
            int pos = idx & (half - 1);
            int grp = idx >> (s-1);
            int i0 = (grp << s) + pos;
            int i1 = i0 + half;
            float2 tw = g_tw[pos << (11 - s)];
            float2 u = S[i0], v = S[i1];
            float tr = tw.x*v.x - tw.y*v.y;
            float ti = tw.x*v.y + tw.y*v.x;
            S[i0] = make_float2(u.x + tr, u.y + ti);
            S[i1] = make_float2(u.x - tr, u.y - ti);
        }
        __syncthreads();
    }

    // harmonic gather with real-FFT unpack: X[k] = Xe[k] + e^{-i pi k/1024} Xo[k]
    float f0v = f0[b*T_FRAMES + t];
    float f0nz = (f0v > 0.0f) ? f0v : 80.0f;
    int rowbase = (t*BATCH + b) * DIN;
    for (int j = tid; j < 300; j += 256) {
        float m = 0.5f * (float)(j + 1);
        float harm = f0nz * m;
        float r = harm / 11.71875f;
        int k = (int)rintf(r);
        k = min(max(k, 0), 1024);
        float p = 0.0f;
        if (k < 1024) {
            int kr = (1024 - k) & 1023;
            float2 a = S[k];
            float2 zr = S[kr];
            float br = zr.x, bi = -zr.y;                 // conj(Z[N-k])
            float xer = 0.5f*(a.x + br), xei = 0.5f*(a.y + bi);
            float dr = a.x - br, di = a.y - bi;
            float xo_r = 0.5f*di, xo_i = -0.5f*dr;       // -i*(a-b)/2
            float sn, cs;
            sincospif((float)k * (1.0f/1024.0f), &sn, &cs);
            float wr = cs, wi = -sn;
            float Xr = xer + wr*xo_r - wi*xo_i;
            float Xi = xei + wr*xo_i + wi*xo_r;
            p = Xr*Xr + Xi*Xi;
        }
        g_feat[rowbase + j] = (logf(p + 1e-8f) + 18.0f) / 23.0f;
    }
    if (tid == 0) g_feat[rowbase + 300] = logf(f0nz);
}

// ---------------------------- input pre-GEMM ------------------------------
__global__ __launch_bounds__(256) void pre_gemm_kernel()
{
    __shared__ float s_feat[16 * DIN];
    int t = blockIdx.x;
    int cb = blockIdx.y * 512;
    int tid = threadIdx.x;

    int base = t * 16 * DIN;
    for (int i = tid; i < 16*DIN; i += 256) s_feat[i] = g_feat[base + i];
    __syncthreads();

    int cl = (tid & 127) * 4 + cb;
    int rh = tid >> 7;
    float4 acc[8];
    float4 bias = *(const float4*)&g_bias[cl];
    #pragma unroll
    for (int r = 0; r < 8; r++) acc[r] = bias;

    const float* fb = s_feat + rh*8*DIN;
    for (int k = 0; k < DIN; k++) {
        float4 w = *(const float4*)&g_wihT[k*1024 + cl];
        #pragma unroll
        for (int r = 0; r < 8; r++) {
            float f = fb[r*DIN + k];
            acc[r].x += f*w.x; acc[r].y += f*w.y; acc[r].z += f*w.z; acc[r].w += f*w.w;
        }
    }
    #pragma unroll
    for (int r = 0; r < 8; r++) {
        int row = t*16 + rh*8 + r;
        *(float4*)&g_pre[row*1024 + cl] = acc[r];
    }
}

// ------------------------------ bi-LSTM ----------------------------------
// fast, overflow-safe sigmoid/tanh via MUFU (EX2 + RCP), rel err ~1e-6
__device__ __forceinline__ float fsigm(float x) {
    float e = __expf(-fabsf(x));
    float inv = __fdividef(1.0f, 1.0f + e);
    return (x >= 0.0f) ? inv : e * inv;
}
__device__ __forceinline__ float ftanh(float x) {
    float e = __expf(-2.0f * fabsf(x));
    float r = __fdividef(1.0f - e, 1.0f + e);
    return copysignf(r, x);
}
__device__ __forceinline__ ull ffma2(ull a, ull b, ull c) {
    ull d;
    asm("fma.rn.f32x2 %0, %1, %2, %3;" : "=l"(d) : "l"(a), "l"(b), "l"(c));
    return d;
}
__device__ __forceinline__ float2 u2f2(ull a) {
    float2 f;
    asm("mov.b64 {%0, %1}, %2;" : "=f"(f.x), "=f"(f.y) : "l"(a));
    return f;
}
#define CLUSTER_SYNC() do { \
    asm volatile("barrier.cluster.arrive.aligned;" ::: "memory"); \
    asm volatile("barrier.cluster.wait.aligned;"   ::: "memory"); \
} while (0)

// cluster of 2 CTAs per (b, d): k-split, register-resident weights.
// Rank-local gate split: rank r owns h rows [64r, 64r+64). Its dot reads ONLY
// those 64 h values (its own k-half), so h is never exchanged. Partials are
// stored permuted — pos = (jg>>6)*256 + q*64 + (jg&63) — so the 256 rows the
// peer needs form one contiguous 1024B slice, published as 8 eager per-warp
// 128B bulk copies completing on the peer's parity mbarrier.
__global__ __launch_bounds__(512, 1) __cluster_dims__(2, 1, 1)
void lstm_kernel()
{
    int cid  = blockIdx.x >> 1;      // 0..31
    int rank = blockIdx.x & 1;       // k-half / h-row half
    int d = cid >> 4, b = cid & 15;
    int g = threadIdx.x;             // gate row 0..511

    // 64 weights (this rank's k-half of row g) as 32 packed f32x2 registers
    ull w2[32];
    {
        const ull* WP = (const ull*)g_whhP + (size_t)(d*64 + rank*32)*512 + g;
        #pragma unroll
        for (int j = 0; j < 32; j++) w2[j] = WP[j*512];
    }

    __shared__ __align__(16) ull   h2_sh[32];          // local h (64 floats)
    __shared__ __align__(16) float partbuf[2][2][512]; // [parity][0=self,1=peer][pos]
    __shared__ __align__(8)  ull   s_bar[2];           // parity-indexed mbarriers

    if (g < 32) h2_sh[g] = 0ULL;
    u32 bar_local  = (u32)__cvta_generic_to_shared(s_bar);
    u32 part_local = (u32)__cvta_generic_to_shared(partbuf);
    if (g == 0) {
        asm volatile("mbarrier.init.shared.b64 [%0], 1;" :: "r"(bar_local)     : "memory");
        asm volatile("mbarrier.init.shared.b64 [%0], 1;" :: "r"(bar_local + 8) : "memory");
        // arm steps 0 and 1 (1024B peer bytes each) before any peer traffic
        asm volatile("mbarrier.arrive.expect_tx.shared.b64 _, [%0], %1;"
                     :: "r"(bar_local),     "r"(1024u) : "memory");
        asm volatile("mbarrier.arrive.expect_tx.shared.b64 _, [%0], %1;"
                     :: "r"(bar_local + 8), "r"(1024u) : "memory");
    }
    float c_state = 0.0f;
    __syncthreads();
    CLUSTER_SYNC();   // peer barriers armed before any bulk copy

    // cluster-mapped peer addresses (hoisted)
    u32 part_peer_c, bar_peer_c;
    asm("mapa.shared::cluster.u32 %0, %1, %2;" : "=r"(part_peer_c) : "r"(part_local), "r"((u32)(rank^1)));
    asm("mapa.shared::cluster.u32 %0, %1, %2;" : "=r"(bar_peer_c)  : "r"(bar_local),  "r"((u32)(rank^1)));

    // permuted partial position for this thread's gate row
    int q  = g >> 7;                 // gate index 0..3 (i,f,g,o)
    int jg = g & 127;                // h-row index
    int halfbit = jg >> 6;           // which rank consumes this row
    u32 pos = (u32)(halfbit*256 + q*64 + (jg & 63));
    bool sendwarp = (halfbit == (rank ^ 1));   // warp-uniform (64-thread granules)
    // lane0 copy source/dst offset: this warp's 32 contiguous pos slots
    u32 wchunk = (pos & ~31u) * 4u;            // byte offset within a [512] buffer

    const float* preB = g_pre + d*512;
    float* hcatB = g_hcat + d*HID + rank*64;
    int jglob = rank*64 + g;         // gate threads g<64: global h row

    // prefetch pre-activations for step 0 (gate threads only)
    float pn0 = 0.f, pn1 = 0.f, pn2 = 0.f, pn3 = 0.f;
    if (g < 64) {
        int t0 = d ? (T_FRAMES - 1) : 0;
        const float* pr = preB + (size_t)(t0*BATCH + b)*1024 + jglob;
        pn0 = pr[0]; pn1 = pr[128]; pn2 = pr[256]; pn3 = pr[384];
    }

    for (int s = 0; s < T_FRAMES; s++) {
        int t = d ? (T_FRAMES - 1 - s) : s;
        int row = t*BATCH + b;
        u32 par = (u32)(s & 1);
        u32 ph  = (u32)((s >> 1) & 1);

        float p0 = pn0, p1 = pn1, p2 = pn2, p3 = pn3;
        if (g < 64 && s + 1 < T_FRAMES) {
            int tn = d ? (T_FRAMES - 2 - s) : (s + 1);
            const float* pr = preB + (size_t)(tn*BATCH + b)*1024 + jglob;
            pn0 = pr[0]; pn1 = pr[128]; pn2 = pr[256]; pn3 = pr[384];
        }

        // partial dot over this rank's k-half (local 64 h values): 32 FFMA2
        ull a0 = 0ULL, a1 = 0ULL, a2 = 0ULL, a3 = 0ULL;
        const ulonglong2* hh = (const ulonglong2*)h2_sh;
        #pragma unroll
        for (int j = 0; j < 8; j++) {
            ulonglong2 hA = hh[2*j], hB = hh[2*j+1];
            a0 = ffma2(w2[4*j+0], hA.x, a0);
            a1 = ffma2(w2[4*j+1], hA.y, a1);
            a2 = ffma2(w2[4*j+2], hB.x, a2);
            a3 = ffma2(w2[4*j+3], hB.y, a3);
        }
        float2 f0v = u2f2(a0), f1v = u2f2(a1), f2v = u2f2(a2), f3v = u2f2(a3);
        float partial = ((f0v.x + f0v.y) + (f1v.x + f1v.y))
                      + ((f2v.x + f2v.y) + (f3v.x + f3v.y));

        partbuf[par][0][pos] = partial;       // local STS (permuted)
        __syncwarp();

        if (sendwarp && (g & 31) == 0) {      // eager per-warp 128B publish
            asm volatile("fence.proxy.async.shared::cta;" ::: "memory");
            u32 off = par*4096u + wchunk;     // [par][0][...] source
            u32 dsto = par*4096u + 2048u + wchunk;  // [par][1][...] dest on peer
            asm volatile("cp.async.bulk.shared::cluster.shared::cta.mbarrier::complete_tx::bytes "
                         "[%0], [%1], %2, [%3];"
                         :: "r"(part_peer_c + dsto), "r"(part_local + off),
                            "r"(128u), "r"(bar_peer_c + 8u*par) : "memory");
        }

        __syncthreads();   // local partials visible (overlaps DSMEM flight)

        // wait for the peer's 1024B slice of this step
        asm volatile("{\n\t"
                     ".reg .pred P;\n"
                     "LW%=:\n\t"
                     "mbarrier.try_wait.parity.acquire.cta.shared::cta.b64 P, [%0], %1, 0x989680;\n\t"
                     "@!P bra LW%=;\n\t"
                     "}" :: "r"(bar_local + 8u*par), "r"(ph) : "memory");

        // re-arm this parity barrier for step s+2 (before we publish s+1)
        if (g == 0 && s + 2 < T_FRAMES) {
            asm volatile("mbarrier.arrive.expect_tx.shared.b64 _, [%0], %1;"
                         :: "r"(bar_local + 8u*par), "r"(1024u) : "memory");
        }

        if (g < 64) {   // this rank's 64 gate rows
            const float* selfp = partbuf[par][0];
            const float* peerp = partbuf[par][1];
            const float* lo = rank ? peerp : selfp;   // rank0 (k-low) first
            const float* hi = rank ? selfp : peerp;
            u32 bse = (u32)(rank*256 + g);
            float zi = (lo[bse]     + hi[bse])     + p0;
            float zf = (lo[bse+64]  + hi[bse+64])  + p1;
            float zg = (lo[bse+128] + hi[bse+128]) + p2;
            float zo = (lo[bse+192] + hi[bse+192]) + p3;
            c_state = fsigm(zf)*c_state + fsigm(zi)*ftanh(zg);
            float h = fsigm(zo)*ftanh(c_state);
            ((float*)h2_sh)[g] = h;
            hcatB[(size_t)row*256 + g] = h;
        }
        __syncthreads();   // h2_sh ready for next step's dot
    }
    CLUSTER_SYNC();        // no CTA exits with peer traffic in flight
}

// ----------------------- LayerNorm + output GEMM --------------------------
__global__ __launch_bounds__(256) void final_kernel(const float* __restrict__ ln_g,
                                                    const float* __restrict__ ln_b,
                                                    const float* __restrict__ out_b,
                                                    float* __restrict__ out)
{
    __shared__ float sh[16*256];
    __shared__ float s_sum[256], s_sq[256];
    __shared__ float s_mu[16], s_rstd[16];

    int t = blockIdx.x, tid = threadIdx.x;
    for (int i = tid; i < 4096; i += 256) sh[i] = g_hcat[t*4096 + i];
    __syncthreads();

    {
        int row = tid >> 4, seg = tid & 15;
        float sm = 0.f, sq = 0.f;
        const float* p = sh + row*256 + seg*16;
        #pragma unroll
        for (int u = 0; u < 16; u++) { float v = p[u]; sm += v; sq += v*v; }
        s_sum[tid] = sm; s_sq[tid] = sq;
    }
    __syncthreads();
    if (tid < 16) {
        float sm = 0.f, sq = 0.f;
        #pragma unroll
        for (int u = 0; u < 16; u++) { sm += s_sum[tid*16 + u]; sq += s_sq[tid*16 + u]; }
        float mu = sm * (1.0f/256.0f);
        float var = sq * (1.0f/256.0f) - mu*mu;
        s_mu[tid] = mu;
        s_rstd[tid] = rsqrtf(var + 1e-5f);
    }
    __syncthreads();
    for (int i = tid; i < 4096; i += 256) {
        int r = i >> 8, k = i & 255;
        sh[i] = (sh[i] - s_mu[r]) * s_rstd[r] * ln_g[k] + ln_b[k];
    }
    __syncthreads();

    int col = tid & 63, rg = tid >> 6;
    float acc[4];
    float bb = out_b[col];
    #pragma unroll
    for (int r = 0; r < 4; r++) acc[r] = bb;
    for (int k = 0; k < 256; k++) {
        float w = g_owT[k*64 + col];
        #pragma unroll
        for (int r = 0; r < 4; r++) acc[r] += sh[(rg*4 + r)*256 + k] * w;
    }
    #pragma unroll
    for (int r = 0; r < 4; r++) {
        int b = rg*4 + r;
        out[(b*T_FRAMES + t)*DOUTN + col] = acc[r];
    }
}

// ------------------------------ launcher ----------------------------------
extern "C" void kernel_launch(void* const* d_in, const int* in_sizes, int n_in,
                              void* d_out, int out_size)
{
    const float* x     = (const float*)d_in[0];
    const float* f0    = (const float*)d_in[1];
    const float* wihf  = (const float*)d_in[2];
    const float* whhf  = (const float*)d_in[3];
    const float* bf    = (const float*)d_in[4];
    const float* wihb  = (const float*)d_in[5];
    const float* whhb  = (const float*)d_in[6];
    const float* bb    = (const float*)d_in[7];
    const float* lng   = (const float*)d_in[8];
    const float* lnb   = (const float*)d_in[9];
    const float* outw  = (const float*)d_in[10];
    const float* outb  = (const float*)d_in[11];
    float* out = (float*)d_out;

    prep_kernel<<<256, 256>>>(wihf, whhf, bf, wihb, whhb, bb, outw);
    stft_kernel<<<dim3(T_FRAMES, BATCH), 256>>>(x, f0);
    pre_gemm_kernel<<<dim3(T_FRAMES, 2), 256>>>();
    lstm_kernel<<<64, 512>>>();
    final_kernel<<<T_FRAMES, 256>>>(lng, lnb, outb, out);
}

// round 12
// speedup vs baseline: 1.4841x; 1.1973x over previous
#include <cuda_runtime.h>
#include <cstdint>
#include <math.h>

#define T_FRAMES 1001
#define BATCH    16
#define LSIG     240000
#define HOP      240
#define DIN      301
#define HID      128
#define DOUTN    64
#define NROWS    (T_FRAMES*BATCH)   // 16016

typedef unsigned long long ull;
typedef unsigned int u32;

// ------------------------- static device scratch -------------------------
__device__ float2 g_tw[1024];                  // twiddles e^{-2pi i k/2048}
__device__ float  g_feat[NROWS * DIN];         // features [row=t*16+b][301]
__device__ float  g_wihT[DIN * 1024];          // transposed input weights [k][g]
__device__ float  g_bias[1024];
__device__ float  g_pre[NROWS * 1024];         // pre-activations [row][1024]
__device__ float2 g_whhP[2 * 64 * 512];        // [d][k2][g] = (W[g][2k2], W[g][2k2+1])
__device__ float  g_hcat[NROWS * 256];         // [row][fwd 0..127 | bwd 128..255]
__device__ float  g_owT[256 * 64];             // out_w transposed [k][o]

// ------------------------------ prep kernel ------------------------------
__global__ void prep_kernel(const float* __restrict__ wihf, const float* __restrict__ whhf,
                            const float* __restrict__ bf,   const float* __restrict__ wihb,
                            const float* __restrict__ whhb, const float* __restrict__ bb,
                            const float* __restrict__ outw)
{
    int tid = blockIdx.x * blockDim.x + threadIdx.x;
    int nth = gridDim.x * blockDim.x;

    for (int k = tid; k < 1024; k += nth) {
        float s, c;
        sincospif((float)k * (1.0f/1024.0f), &s, &c);
        g_tw[k] = make_float2(c, -s);
    }
    for (int i = tid; i < DIN*1024; i += nth) {
        int g = i & 1023, k = i >> 10;
        g_wihT[i] = (g < 512) ? wihf[g*DIN + k] : wihb[(g-512)*DIN + k];
    }
    for (int g = tid; g < 1024; g += nth)
        g_bias[g] = (g < 512) ? bf[g] : bb[g-512];
    for (int i = tid; i < 2*64*512; i += nth) {
        int d = i >> 15;
        int k2 = (i >> 9) & 63;
        int g = i & 511;
        const float* W = d ? whhb : whhf;
        g_whhP[i] = make_float2(W[g*HID + 2*k2], W[g*HID + 2*k2 + 1]);
    }
    for (int i = tid; i < 256*64; i += nth) {
        int o = i & 63, k = i >> 6;
        g_owT[i] = outw[o*256 + k];
    }
}

// ---------------------- STFT (real-packed) + features ---------------------
__device__ __forceinline__ float wsamp(const float* __restrict__ xb, int t, int j)
{
    int q = t*HOP + j - 1024;
    if (q < 0) q = -q;
    else if (q >= LSIG) q = 2*LSIG - 2 - q;
    int jw = j - 544;
    float wv = (jw >= 0 && jw < 960) ? (0.5f - 0.5f*cospif((float)jw * (1.0f/480.0f))) : 0.0f;
    return xb[q] * wv;
}

__global__ __launch_bounds__(256) void stft_kernel(const float* __restrict__ x,
                                                   const float* __restrict__ f0)
{
    __shared__ float2 S[1024];
    int t = blockIdx.x, b = blockIdx.y, tid = threadIdx.x;
    const float* xb = x + b * LSIG;

    for (int n = tid; n < 1024; n += 256) {
        float v0 = wsamp(xb, t, 2*n);
        float v1 = wsamp(xb, t, 2*n + 1);
        int rev = __brev((unsigned)n) >> 22;
        S[rev] = make_float2(v0, v1);
    }
    __syncthreads();

    #pragma unroll
    for (int s = 1; s <= 10; s++) {
        int half = 1 << (s-1);
        for (int idx = tid; idx < 512; idx += 256) {
            int pos = idx & (half - 1);
            int grp = idx >> (s-1);
            int i0 = (grp << s) + pos;
            int i1 = i0 + half;
            float2 tw = g_tw[pos << (11 - s)];
            float2 u = S[i0], v = S[i1];
            float tr = tw.x*v.x - tw.y*v.y;
            float ti = tw.x*v.y + tw.y*v.x;
            S[i0] = make_float2(u.x + tr, u.y + ti);
            S[i1] = make_float2(u.x - tr, u.y - ti);
        }
        __syncthreads();
    }

    float f0v = f0[b*T_FRAMES + t];
    float f0nz = (f0v > 0.0f) ? f0v : 80.0f;
    int rowbase = (t*BATCH + b) * DIN;
    for (int j = tid; j < 300; j += 256) {
        float m = 0.5f * (float)(j + 1);
        float harm = f0nz * m;
        float r = harm / 11.71875f;
        int k = (int)rintf(r);
        k = min(max(k, 0), 1024);
        float p = 0.0f;
        if (k < 1024) {
            int kr = (1024 - k) & 1023;
            float2 a = S[k];
            float2 zr = S[kr];
            float br = zr.x, bi = -zr.y;
            float xer = 0.5f*(a.x + br), xei = 0.5f*(a.y + bi);
            float dr = a.x - br, di = a.y - bi;
            float xo_r = 0.5f*di, xo_i = -0.5f*dr;
            float sn, cs;
            sincospif((float)k * (1.0f/1024.0f), &sn, &cs);
            float wr = cs, wi = -sn;
            float Xr = xer + wr*xo_r - wi*xo_i;
            float Xi = xei + wr*xo_i + wi*xo_r;
            p = Xr*Xr + Xi*Xi;
        }
        g_feat[rowbase + j] = (logf(p + 1e-8f) + 18.0f) / 23.0f;
    }
    if (tid == 0) g_feat[rowbase + 300] = logf(f0nz);
}

// ---------------------------- input pre-GEMM ------------------------------
__global__ __launch_bounds__(256) void pre_gemm_kernel()
{
    __shared__ float s_feat[16 * DIN];
    int t = blockIdx.x;
    int cb = blockIdx.y * 512;
    int tid = threadIdx.x;

    int base = t * 16 * DIN;
    for (int i = tid; i < 16*DIN; i += 256) s_feat[i] = g_feat[base + i];
    __syncthreads();

    int cl = (tid & 127) * 4 + cb;
    int rh = tid >> 7;
    float4 acc[8];
    float4 bias = *(const float4*)&g_bias[cl];
    #pragma unroll
    for (int r = 0; r < 8; r++) acc[r] = bias;

    const float* fb = s_feat + rh*8*DIN;
    for (int k = 0; k < DIN; k++) {
        float4 w = *(const float4*)&g_wihT[k*1024 + cl];
        #pragma unroll
        for (int r = 0; r < 8; r++) {
            float f = fb[r*DIN + k];
            acc[r].x += f*w.x; acc[r].y += f*w.y; acc[r].z += f*w.z; acc[r].w += f*w.w;
        }
    }
    #pragma unroll
    for (int r = 0; r < 8; r++) {
        int row = t*16 + rh*8 + r;
        *(float4*)&g_pre[row*1024 + cl] = acc[r];
    }
}

// ------------------------------ bi-LSTM ----------------------------------
__device__ __forceinline__ float fsigm(float x) {
    float e = __expf(-fabsf(x));
    float inv = __fdividef(1.0f, 1.0f + e);
    return (x >= 0.0f) ? inv : e * inv;
}
__device__ __forceinline__ float ftanh(float x) {
    float e = __expf(-2.0f * fabsf(x));
    float r = __fdividef(1.0f - e, 1.0f + e);
    return copysignf(r, x);
}
__device__ __forceinline__ ull ffma2(ull a, ull b, ull c) {
    ull d;
    asm("fma.rn.f32x2 %0, %1, %2, %3;" : "=l"(d) : "l"(a), "l"(b), "l"(c));
    return d;
}
__device__ __forceinline__ float2 u2f2(ull a) {
    float2 f;
    asm("mov.b64 {%0, %1}, %2;" : "=f"(f.x), "=f"(f.y) : "l"(a));
    return f;
}
#define CLUSTER_SYNC() do { \
    asm volatile("barrier.cluster.arrive.aligned;" ::: "memory"); \
    asm volatile("barrier.cluster.wait.aligned;"   ::: "memory"); \
} while (0)

// cluster of 2 CTAs per (b, d). Scheme H: rank r owns h rows [64r,64r+64) and
// computes the FULL k=128 dot for its 256 gate rows, 2 threads per row
// (k-halves). Only h crosses CTAs: 64 floats = 256B per step, sent by the 64
// gate threads as single st.async stores the moment h is produced. Next step,
// own-k-half threads start immediately on local h; only peer-k-half threads
// wait on the parity mbarrier — the DSMEM flight overlaps the local half-dot.
__global__ __launch_bounds__(512, 1) __cluster_dims__(2, 1, 1)
void lstm_kernel()
{
    int cid  = blockIdx.x >> 1;      // 0..31
    int rank = blockIdx.x & 1;       // h-row half owned
    int d = cid >> 4, b = cid & 15;
    int tid = threadIdx.x;
    int u  = tid >> 8;               // k-half this thread computes (0: k<64, 1: k>=64)
    int rl = tid & 255;              // local gate row = q*64 + j
    int q  = rl >> 6;                // gate (i,f,g,o)
    int j  = rl & 63;                // own h row index
    int grow = q*128 + rank*64 + j;  // global W row

    // this thread's 64 weights (k in [64u, 64u+64)) as 32 packed f32x2
    ull w2[32];
    {
        const ull* WP = (const ull*)g_whhP + ((size_t)d*64 + 32*u)*512 + grow;
        #pragma unroll
        for (int jj = 0; jj < 32; jj++) w2[jj] = WP[jj*512];
    }

    __shared__ __align__(16) ull   h_own2[32];      // own 64 h
    __shared__ __align__(16) ull   hpeer2[2][32];   // peer 64 h, parity buffers
    __shared__ float part_sh[512];                  // [u*256 + rl]
    __shared__ __align__(8) ull    s_bar[2];        // parity mbarriers

    if (tid < 32) { h_own2[tid] = 0ULL; hpeer2[0][tid] = 0ULL; hpeer2[1][tid] = 0ULL; }
    u32 bar_local   = (u32)__cvta_generic_to_shared(s_bar);
    u32 hpeer_local = (u32)__cvta_generic_to_shared(hpeer2);
    if (tid == 0) {
        asm volatile("mbarrier.init.shared.b64 [%0], 1;" :: "r"(bar_local)     : "memory");
        asm volatile("mbarrier.init.shared.b64 [%0], 1;" :: "r"(bar_local + 8) : "memory");
        // arm steps 0 and 1: 256B of peer h each
        asm volatile("mbarrier.arrive.expect_tx.shared.b64 _, [%0], %1;"
                     :: "r"(bar_local),     "r"(256u) : "memory");
        asm volatile("mbarrier.arrive.expect_tx.shared.b64 _, [%0], %1;"
                     :: "r"(bar_local + 8), "r"(256u) : "memory");
    }
    float c_state = 0.0f;
    __syncthreads();
    CLUSTER_SYNC();   // peer barriers armed before any st.async

    u32 hpeer_c, bar_peer_c;
    asm("mapa.shared::cluster.u32 %0, %1, %2;" : "=r"(hpeer_c)   : "r"(hpeer_local), "r"((u32)(rank^1)));
    asm("mapa.shared::cluster.u32 %0, %1, %2;" : "=r"(bar_peer_c): "r"(bar_local),   "r"((u32)(rank^1)));

    const float* preB = g_pre + d*512;
    float* hcatB = g_hcat + d*HID + rank*64;
    int jglob = rank*64 + tid;       // gate threads (tid<64): global h row

    // prologue: deliver h0 = 0 for step 0 to the peer's parity-0 buffer
    if (tid < 64) {
        asm volatile("st.async.shared::cluster.mbarrier::complete_tx::bytes.b32 [%0], %1, [%2];"
                     :: "r"(hpeer_c + (u32)tid*4u), "r"(0u), "r"(bar_peer_c) : "memory");
    }

    // prefetch pre-activations for step 0 (gate threads only)
    float pn0 = 0.f, pn1 = 0.f, pn2 = 0.f, pn3 = 0.f;
    if (tid < 64) {
        int t0 = d ? (T_FRAMES - 1) : 0;
        const float* pr = preB + (size_t)(t0*BATCH + b)*1024 + jglob;
        pn0 = pr[0]; pn1 = pr[128]; pn2 = pr[256]; pn3 = pr[384];
    }

    bool iswait = (u != rank);       // threads needing peer h
    for (int s = 0; s < T_FRAMES; s++) {
        int t = d ? (T_FRAMES - 1 - s) : s;
        int row = t*BATCH + b;
        u32 par = (u32)(s & 1);
        u32 ph  = (u32)((s >> 1) & 1);

        float p0 = pn0, p1 = pn1, p2 = pn2, p3 = pn3;
        if (tid < 64 && s + 1 < T_FRAMES) {
            int tn = d ? (T_FRAMES - 2 - s) : (s + 1);
            const float* pr = preB + (size_t)(tn*BATCH + b)*1024 + jglob;
            pn0 = pr[0]; pn1 = pr[128]; pn2 = pr[256]; pn3 = pr[384];
        }

        // peer-k-half threads wait for this step's peer h (own-half threads run ahead)
        if (iswait) {
            asm volatile("{\n\t"
                         ".reg .pred P;\n"
                         "LW%=:\n\t"
                         "mbarrier.try_wait.parity.acquire.cta.shared::cta.b64 P, [%0], %1, 0x989680;\n\t"
                         "@!P bra LW%=;\n\t"
                         "}" :: "r"(bar_local + 8u*par), "r"(ph) : "memory");
            if (rl == 0 && s + 2 < T_FRAMES) {   // re-arm this parity for step s+2
                asm volatile("mbarrier.arrive.expect_tx.shared.b64 _, [%0], %1;"
                             :: "r"(bar_local + 8u*par), "r"(256u) : "memory");
            }
        }

        // full-row partial over this thread's k-half: 32 packed FFMA2
        const ulonglong2* hh = iswait ? (const ulonglong2*)hpeer2[par]
                                      : (const ulonglong2*)h_own2;
        ull a0 = 0ULL, a1 = 0ULL, a2 = 0ULL, a3 = 0ULL;
        #pragma unroll
        for (int jj = 0; jj < 8; jj++) {
            ulonglong2 hA = hh[2*jj], hB = hh[2*jj+1];
            a0 = ffma2(w2[4*jj+0], hA.x, a0);
            a1 = ffma2(w2[4*jj+1], hA.y, a1);
            a2 = ffma2(w2[4*jj+2], hB.x, a2);
            a3 = ffma2(w2[4*jj+3], hB.y, a3);
        }
        float2 f0v = u2f2(a0), f1v = u2f2(a1), f2v = u2f2(a2), f3v = u2f2(a3);
        part_sh[tid] = ((f0v.x + f0v.y) + (f1v.x + f1v.y))
                     + ((f2v.x + f2v.y) + (f3v.x + f3v.y));
        __syncthreads();

        if (tid < 64) {   // one gate thread per own h row
            // fixed order: (k-low + k-high) + pre
            float zi = (part_sh[tid]     + part_sh[256+tid]) + p0;
            float zf = (part_sh[64+tid]  + part_sh[320+tid]) + p1;
            float zg = (part_sh[128+tid] + part_sh[384+tid]) + p2;
            float zo = (part_sh[192+tid] + part_sh[448+tid]) + p3;
            c_state = fsigm(zf)*c_state + fsigm(zi)*ftanh(zg);
            float h = fsigm(zo)*ftanh(c_state);
            ((float*)h_own2)[tid] = h;
            hcatB[(size_t)row*256 + tid] = h;
            if (s + 1 < T_FRAMES) {   // ship h to peer's next-parity buffer
                asm volatile("st.async.shared::cluster.mbarrier::complete_tx::bytes.b32 [%0], %1, [%2];"
                             :: "r"(hpeer_c + (par^1u)*256u + (u32)tid*4u),
                                "r"(__float_as_uint(h)),
                                "r"(bar_peer_c + 8u*(par^1u)) : "memory");
            }
        }
        __syncthreads();   // h_own2 ready for next step's own-half dot
    }
    CLUSTER_SYNC();        // no CTA exits with peer traffic in flight
}

// ----------------------- LayerNorm + output GEMM --------------------------
__global__ __launch_bounds__(256) void final_kernel(const float* __restrict__ ln_g,
                                                    const float* __restrict__ ln_b,
                                                    const float* __restrict__ out_b,
                                                    float* __restrict__ out)
{
    __shared__ float sh[16*256];
    __shared__ float s_sum[256], s_sq[256];
    __shared__ float s_mu[16], s_rstd[16];

    int t = blockIdx.x, tid = threadIdx.x;
    for (int i = tid; i < 4096; i += 256) sh[i] = g_hcat[t*4096 + i];
    __syncthreads();

    {
        int row = tid >> 4, seg = tid & 15;
        float sm = 0.f, sq = 0.f;
        const float* p = sh + row*256 + seg*16;
        #pragma unroll
        for (int u = 0; u < 16; u++) { float v = p[u]; sm += v; sq += v*v; }
        s_sum[tid] = sm; s_sq[tid] = sq;
    }
    __syncthreads();
    if (tid < 16) {
        float sm = 0.f, sq = 0.f;
        #pragma unroll
        for (int u = 0; u < 16; u++) { sm += s_sum[tid*16 + u]; sq += s_sq[tid*16 + u]; }
        float mu = sm * (1.0f/256.0f);
        float var = sq * (1.0f/256.0f) - mu*mu;
        s_mu[tid] = mu;
        s_rstd[tid] = rsqrtf(var + 1e-5f);
    }
    __syncthreads();
    for (int i = tid; i < 4096; i += 256) {
        int r = i >> 8, k = i & 255;
        sh[i] = (sh[i] - s_mu[r]) * s_rstd[r] * ln_g[k] + ln_b[k];
    }
    __syncthreads();

    int col = tid & 63, rg = tid >> 6;
    float acc[4];
    float bb = out_b[col];
    #pragma unroll
    for (int r = 0; r < 4; r++) acc[r] = bb;
    for (int k = 0; k < 256; k++) {
        float w = g_owT[k*64 + col];
        #pragma unroll
        for (int r = 0; r < 4; r++) acc[r] += sh[(rg*4 + r)*256 + k] * w;
    }
    #pragma unroll
    for (int r = 0; r < 4; r++) {
        int b = rg*4 + r;
        out[(b*T_FRAMES + t)*DOUTN + col] = acc[r];
    }
}

// ------------------------------ launcher ----------------------------------
extern "C" void kernel_launch(void* const* d_in, const int* in_sizes, int n_in,
                              void* d_out, int out_size)
{
    const float* x     = (const float*)d_in[0];
    const float* f0    = (const float*)d_in[1];
    const float* wihf  = (const float*)d_in[2];
    const float* whhf  = (const float*)d_in[3];
    const float* bf    = (const float*)d_in[4];
    const float* wihb  = (const float*)d_in[5];
    const float* whhb  = (const float*)d_in[6];
    const float* bb    = (const float*)d_in[7];
    const float* lng   = (const float*)d_in[8];
    const float* lnb   = (const float*)d_in[9];
    const float* outw  = (const float*)d_in[10];
    const float* outb  = (const float*)d_in[11];
    float* out = (float*)d_out;

    prep_kernel<<<256, 256>>>(wihf, whhf, bf, wihb, whhb, bb, outw);
    stft_kernel<<<dim3(T_FRAMES, BATCH), 256>>>(x, f0);
    pre_gemm_kernel<<<dim3(T_FRAMES, 2), 256>>>();
    lstm_kernel<<<64, 512>>>();
    final_kernel<<<T_FRAMES, 256>>>(lng, lnb, outb, out);
}